// round 14
// baseline (speedup 1.0000x reference)
#include <cuda_runtime.h>
#include <cuda_fp16.h>
#include <cstdint>

typedef __half f16;

#define Bdim 4
#define Ndim 2048
#define Fdim 256
#define Odim 256
#define Hdim 8
#define BHdim 32
#define HF   2048

// ---------------- scratch (static device globals; no cudaMalloc) ----------
__device__ __align__(16) f16  g_Xhi [(size_t)Bdim*Ndim*Fdim];
__device__ __align__(16) f16  g_WThi[(size_t)Hdim*Fdim*Fdim];
__device__ __align__(16) f16  g_WoThi[(size_t)Odim*HF];
__device__ __align__(16) f16  g_xwhi[(size_t)BHdim*Ndim*Fdim];
__device__ __align__(16) f16  g_mhi [(size_t)Bdim*Ndim*HF];

// ---------------- low-level helpers ----------------------------------------
__device__ __forceinline__ uint32_t smem_u32(const void* p) {
    uint32_t a;
    asm("{ .reg .u64 t; cvta.to.shared.u64 t, %1; cvt.u32.u64 %0, t; }"
        : "=r"(a) : "l"(p));
    return a;
}
#define SWZ(o) ((o) ^ (((o) >> 3) & 0x70))   // SW128: 16B-chunk ^= row%8

__device__ __forceinline__ void cp16(uint32_t dst, const void* src) {
    asm volatile("cp.async.cg.shared.global [%0], [%1], 16;" :: "r"(dst), "l"(src));
}
__device__ __forceinline__ void cp_commit() {
    asm volatile("cp.async.commit_group;");
}
template<int N> __device__ __forceinline__ void cp_wait() {
    asm volatile("cp.async.wait_group %0;" :: "n"(N) : "memory");
}
__device__ __forceinline__ void ldsm4(uint32_t& r0, uint32_t& r1, uint32_t& r2,
                                      uint32_t& r3, uint32_t addr) {
    asm volatile("ldmatrix.sync.aligned.m8n8.x4.shared.b16 {%0,%1,%2,%3}, [%4];"
                 : "=r"(r0), "=r"(r1), "=r"(r2), "=r"(r3) : "r"(addr));
}
__device__ __forceinline__ void ldsm4t(uint32_t& r0, uint32_t& r1, uint32_t& r2,
                                       uint32_t& r3, uint32_t addr) {
    asm volatile("ldmatrix.sync.aligned.m8n8.x4.trans.shared.b16 {%0,%1,%2,%3}, [%4];"
                 : "=r"(r0), "=r"(r1), "=r"(r2), "=r"(r3) : "r"(addr));
}
__device__ __forceinline__ void mma16816(float* c, const uint32_t* a, const uint32_t* b) {
    asm volatile(
        "mma.sync.aligned.m16n8k16.row.col.f32.f16.f16.f32 "
        "{%0,%1,%2,%3},{%4,%5,%6,%7},{%8,%9},{%0,%1,%2,%3};"
        : "+f"(c[0]), "+f"(c[1]), "+f"(c[2]), "+f"(c[3])
        : "r"(a[0]), "r"(a[1]), "r"(a[2]), "r"(a[3]), "r"(b[0]), "r"(b[1]));
}

#define TILE_B  16384                   // 128 rows x 64 f16 (128B rows)
#define STAGE_B (2 * TILE_B)            // A, B
#define SMEM_SZ (2 * STAGE_B)           // 65536 bytes, double buffered

// ---------------- plain fp16 HMMA GEMM core (xw & out stages) --------------
// C(128x128) = A[m,k] * B[n,k]   (K-major, NT)
// MODE 1: Chi = round(acc)     MODE 2: Cf = acc + bias
template<int MODE>
__device__ __forceinline__ void gemm_core(
    const f16* __restrict__ A, int lda,
    const f16* __restrict__ B, int ldb,
    int K,
    float* __restrict__ Cf, f16* __restrict__ Chi,
    int ldc, const float* __restrict__ bias)
{
    extern __shared__ char smem[];
    const uint32_t sb = smem_u32(smem);
    const int tid = threadIdx.x;
    const int wid = tid >> 5, lane = tid & 31;
    const int wm = wid >> 2, wn = wid & 3;        // warp grid 2 x 4
    const int bm = blockIdx.y * 128, bn = blockIdx.x * 128;

    auto load_chunk = [&](int stage, int k0) {
        const uint32_t sbase = sb + stage * STAGE_B;
#pragma unroll
        for (int i = 0; i < 8; i++) {
            int idx = i * 256 + tid;
            int arr = idx >> 10;                   // 0..1
            int r   = (idx >> 3) & 127;
            int c   = idx & 7;
            uint32_t dst = sbase + arr * TILE_B + SWZ((uint32_t)(r * 128 + c * 16));
            const f16* src = (arr == 0)
                ? A + (size_t)(bm + r) * lda + k0 + c * 8
                : B + (size_t)(bn + r) * ldb + k0 + c * 8;
            cp16(dst, src);
        }
        cp_commit();
    };

    float acc[4][4][4];
#pragma unroll
    for (int i = 0; i < 4; i++)
#pragma unroll
        for (int j = 0; j < 4; j++)
#pragma unroll
            for (int q = 0; q < 4; q++) acc[i][j][q] = 0.0f;

    const int NC = K >> 6;
    load_chunk(0, 0);

    const int a_row = wm * 64 + (lane & 15);
    const int a_c16 = (lane >> 4) * 16;
    const int b_row = wn * 32 + (lane & 7) + ((lane >> 4) << 3);
    const int b_c16 = ((lane >> 3) & 1) * 16;

    for (int c = 0; c < NC; c++) {
        const int stage = c & 1;
        if (c + 1 < NC) { load_chunk(stage ^ 1, (c + 1) * 64); cp_wait<1>(); }
        else            { cp_wait<0>(); }
        __syncthreads();

        const uint32_t sA = sb + stage * STAGE_B;
        const uint32_t sB = sA + TILE_B;

#pragma unroll
        for (int s4 = 0; s4 < 4; s4++) {
            const int kb = s4 * 32;
            uint32_t bhi[4][2];
#pragma unroll
            for (int jj = 0; jj < 2; jj++) {
                uint32_t off = SWZ((uint32_t)((b_row + jj * 16) * 128 + kb + b_c16));
                ldsm4(bhi[jj*2][0], bhi[jj*2][1], bhi[jj*2+1][0], bhi[jj*2+1][1], sB + off);
            }
#pragma unroll
            for (int i = 0; i < 4; i++) {
                uint32_t off = SWZ((uint32_t)((a_row + i * 16) * 128 + kb + a_c16));
                uint32_t ahi[4];
                ldsm4(ahi[0], ahi[1], ahi[2], ahi[3], sA + off);
#pragma unroll
                for (int j = 0; j < 4; j++)
                    mma16816(acc[i][j], ahi, bhi[j]);
            }
        }
        __syncthreads();
    }

    const int er = lane >> 2;
    const int ec = (lane & 3) * 2;
#pragma unroll
    for (int i = 0; i < 4; i++) {
#pragma unroll
        for (int j = 0; j < 4; j++) {
            const int n0 = bn + wn * 32 + j * 8 + ec;
#pragma unroll
            for (int half = 0; half < 2; half++) {
                const int m = bm + wm * 64 + i * 16 + er + half * 8;
                float v0 = acc[i][j][half * 2 + 0];
                float v1 = acc[i][j][half * 2 + 1];
                size_t go = (size_t)m * ldc + n0;
                if (MODE == 1) {
                    *(__half2*)(Chi + go) =
                        __halves2half2(__float2half_rn(v0), __float2half_rn(v1));
                } else {
                    float2 o; o.x = v0 + bias[n0]; o.y = v1 + bias[n0 + 1];
                    *(float2*)(Cf + go) = o;
                }
            }
        }
    }
}

__global__ __launch_bounds__(256, 1) void k_mm_xw() {
    int z = blockIdx.z, b = z >> 3, h = z & 7;
    gemm_core<1>(g_Xhi + (size_t)b * Ndim * Fdim, Fdim,
                 g_WThi + (size_t)h * Fdim * Fdim, Fdim,
                 Fdim, nullptr,
                 g_xwhi + (size_t)z * Ndim * Fdim, Fdim, nullptr);
}
__global__ __launch_bounds__(256, 1) void k_mm_out(float* __restrict__ out,
                                                   const float* __restrict__ bias) {
    gemm_core<2>(g_mhi, HF, g_WoThi, HF, HF,
                 out, nullptr, Odim, bias);
}

// ============================================================================
// Fused flash attention, unnormalized softmax, 2 CTAs/SM.
// Q block 64, KV tile 128, single K buffer (cross-CTA overlap hides loads).
// Per tile: [K ready sync] S-MMA, exp+P write, [sync] PV, [sync] issue K(t+1).
// SMEM per CTA: Q 32K | K 64K | P 16K | red 1K = 113K  (2 CTAs = 226K/SM)
// ============================================================================
#define FQoff 0
#define FKoff 32768
#define FPoff 98304
#define RSUMoff 114688
#define FSMEM 115712

__global__ __launch_bounds__(256, 2) void k_flash() {
    extern __shared__ char smem[];
    const uint32_t sb = smem_u32(smem);
    const int tid = threadIdx.x, lane = tid & 31, wid = tid >> 5;
    const int wm = wid >> 2, wn = wid & 3;
    const int z = blockIdx.y, b = z >> 3, h = z & 7;
    const int qb = blockIdx.x;

    const f16* Qhi = g_xwhi + (size_t)z * Ndim * Fdim;
    const f16* Khi = g_Xhi  + (size_t)b * Ndim * Fdim;

    // whole K tile (128 x 256 f16 = 64KB) in one group
    auto load_K_tile = [&](int kv0) {
#pragma unroll
        for (int i = 0; i < 16; i++) {
            int idx = i * 256 + tid;
            int c = idx >> 10;                // chunk 0..3
            int r = (idx >> 3) & 127, cc = idx & 7;
            const f16* src = Khi + (size_t)(kv0 + r) * Fdim + c * 64 + cc * 8;
            cp16(sb + FKoff + c * 16384 + SWZ((uint32_t)(r * 128 + cc * 16)), src);
        }
        cp_commit();
    };

    // ---- prologue: Q (resident) + K(0) ----
#pragma unroll
    for (int i = 0; i < 8; i++) {
        int idx = i * 256 + tid;
        int kc = idx >> 9;                    // 0..3
        int r = (idx >> 3) & 63, cc = idx & 7;
        const f16* src = Qhi + (size_t)(qb * 64 + r) * Fdim + kc * 64 + cc * 8;
        cp16(sb + FQoff + kc * 8192 + SWZ((uint32_t)(r * 128 + cc * 16)), src);
    }
    load_K_tile(0);                           // Q + K(0) in one commit group

    float oacc[2][8][4];
#pragma unroll
    for (int i = 0; i < 2; i++)
#pragma unroll
        for (int j = 0; j < 8; j++)
#pragma unroll
            for (int q = 0; q < 4; q++) oacc[i][j][q] = 0.0f;
    float sacc[2][4][4];
    float lsum[2][2] = {{0.f, 0.f}, {0.f, 0.f}};   // per-thread partial row sums

    const int a_row  = wm * 32 + (lane & 15);
    const int a_c16  = (lane >> 4) * 16;
    const int bk_row = wn * 32 + (lane & 7) + ((lane >> 4) << 3);
    const int b_c16  = ((lane >> 3) & 1) * 16;
    const int tv_row = lane & 15;
    const int tv_c16 = (lane >> 4) * 16;

    float* redsum = (float*)(smem + RSUMoff);

    for (int t = 0; t < 16; t++) {
        cp_wait<0>();
        __syncthreads();                      // K(t) (and Q at t=0) ready

        // ---- S = Q·K over all 4 f-chunks, back-to-back ----
#pragma unroll
        for (int i = 0; i < 2; i++)
#pragma unroll
            for (int j = 0; j < 4; j++)
#pragma unroll
                for (int q = 0; q < 4; q++) sacc[i][j][q] = 0.0f;
#pragma unroll
        for (int c = 0; c < 4; c++) {
            uint32_t qh = sb + FQoff + c * 8192;
            uint32_t kh = sb + FKoff + c * 16384;
#pragma unroll
            for (int s4 = 0; s4 < 4; s4++) {
                int kb2 = s4 * 32;
                uint32_t bh[4][2];
#pragma unroll
                for (int jj = 0; jj < 2; jj++) {
                    uint32_t off = SWZ((uint32_t)((bk_row + jj * 16) * 128 + kb2 + b_c16));
                    ldsm4(bh[jj*2][0], bh[jj*2][1], bh[jj*2+1][0], bh[jj*2+1][1], kh + off);
                }
#pragma unroll
                for (int i = 0; i < 2; i++) {
                    uint32_t off = SWZ((uint32_t)((a_row + i * 16) * 128 + kb2 + a_c16));
                    uint32_t ah[4];
                    ldsm4(ah[0], ah[1], ah[2], ah[3], qh + off);
#pragma unroll
                    for (int j = 0; j < 4; j++)
                        mma16816(sacc[i][j], ah, bh[j]);
                }
            }
        }

        // ---- unnormalized softmax: P = exp(S/16); accumulate local sums ----
#pragma unroll
        for (int i = 0; i < 2; i++)
#pragma unroll
            for (int j = 0; j < 4; j++) {
                float p00 = __expf(sacc[i][j][0] * 0.0625f);
                float p01 = __expf(sacc[i][j][1] * 0.0625f);
                float p10 = __expf(sacc[i][j][2] * 0.0625f);
                float p11 = __expf(sacc[i][j][3] * 0.0625f);
                lsum[i][0] += p00 + p01;
                lsum[i][1] += p10 + p11;
                int col = wn * 32 + j * 8 + (lane & 3) * 2;
                int chunk = col >> 6, cc = col & 63;
#pragma unroll
                for (int hf = 0; hf < 2; hf++) {
                    int r = wm * 32 + i * 16 + (lane >> 2) + hf * 8;
                    uint32_t off = SWZ((uint32_t)(r * 128 + cc * 2));
                    *(__half2*)(smem + FPoff + chunk * 8192 + off) =
                        (hf == 0) ? __halves2half2(__float2half_rn(p00), __float2half_rn(p01))
                                  : __halves2half2(__float2half_rn(p10), __float2half_rn(p11));
                }
            }
        __syncthreads();                      // P visible to all warps

        // ---- PV: O += P · K^T (V = K chunk wn via ldmatrix.trans) ----
        {
            uint32_t vh = sb + FKoff + wn * 16384;
#pragma unroll
            for (int kc = 0; kc < 2; kc++) {
                uint32_t ph = sb + FPoff + kc * 8192;
#pragma unroll
                for (int s4 = 0; s4 < 4; s4++) {
                    int kr = kc * 64 + s4 * 16;
                    uint32_t bh[8][2];
#pragma unroll
                    for (int jh = 0; jh < 4; jh++) {
                        uint32_t off = SWZ((uint32_t)((kr + tv_row) * 128 + jh * 32 + tv_c16));
                        ldsm4t(bh[jh*2][0], bh[jh*2][1], bh[jh*2+1][0], bh[jh*2+1][1], vh + off);
                    }
#pragma unroll
                    for (int i = 0; i < 2; i++) {
                        uint32_t off = SWZ((uint32_t)((a_row + i * 16) * 128 + s4 * 32 + a_c16));
                        uint32_t p4h[4];
                        ldsm4(p4h[0], p4h[1], p4h[2], p4h[3], ph + off);
#pragma unroll
                        for (int j = 0; j < 8; j++)
                            mma16816(oacc[i][j], p4h, bh[j]);
                    }
                }
            }
        }
        __syncthreads();                      // PV done reading K & P
        if (t + 1 < 16) load_K_tile((t + 1) * 128);
    }

    // ---- epilogue: reduce lsum across lanes & n-warps, then O/l -> g_mhi ----
#pragma unroll
    for (int i = 0; i < 2; i++)
#pragma unroll
        for (int hf = 0; hf < 2; hf++) {
            float ts = lsum[i][hf];
            ts += __shfl_xor_sync(0xffffffffu, ts, 1);
            ts += __shfl_xor_sync(0xffffffffu, ts, 2);
            if ((lane & 3) == 0) {
                int r = wm * 32 + i * 16 + (lane >> 2) + hf * 8;
                redsum[wn * 64 + r] = ts;
            }
        }
    __syncthreads();

#pragma unroll
    for (int i = 0; i < 2; i++)
#pragma unroll
        for (int hf = 0; hf < 2; hf++) {
            int r = wm * 32 + i * 16 + (lane >> 2) + hf * 8;
            int n = qb * 64 + r;
            float l = redsum[r] + redsum[64 + r] + redsum[128 + r] + redsum[192 + r];
            float invl = 1.0f / l;
#pragma unroll
            for (int j = 0; j < 8; j++) {
                int col = h * 256 + wn * 64 + j * 8 + (lane & 3) * 2;
                float v0 = oacc[i][j][hf * 2] * invl;
                float v1 = oacc[i][j][hf * 2 + 1] * invl;
                size_t go = ((size_t)b * Ndim + n) * HF + col;
                *(__half2*)(g_mhi + go) =
                    __halves2half2(__float2half_rn(v0), __float2half_rn(v1));
            }
        }
}

// ---------------- convert / transpose-convert -------------------------------
__global__ __launch_bounds__(256) void k_split_nodes(const float* __restrict__ x) {
    int i = blockIdx.x * 256 + threadIdx.x;
    g_Xhi[i] = __float2half_rn(x[i]);
}

__device__ __forceinline__ void tcvt_core(const float* __restrict__ src,
                                          f16* __restrict__ hi, int R, int C) {
    __shared__ float t[32][33];
    size_t mo = (size_t)blockIdx.z * R * C;
    src += mo; hi += mo;
    int c0 = blockIdx.x * 32, r0 = blockIdx.y * 32;
    int tx = threadIdx.x & 31, ty = threadIdx.x >> 5;
#pragma unroll
    for (int k = 0; k < 4; k++)
        t[ty + k * 8][tx] = src[(size_t)(r0 + ty + k * 8) * C + c0 + tx];
    __syncthreads();
#pragma unroll
    for (int k = 0; k < 4; k++) {
        int rr = ty + k * 8;
        hi[(size_t)(c0 + rr) * R + r0 + tx] = __float2half_rn(t[tx][rr]);
    }
}
__global__ __launch_bounds__(256) void k_cvt_WT(const float* __restrict__ W) {
    tcvt_core(W, g_WThi, Fdim, Fdim);
}
__global__ __launch_bounds__(256) void k_cvt_WoT(const float* __restrict__ Wo) {
    tcvt_core(Wo, g_WoThi, HF, Odim);
}

// ---------------- launch ------------------------------------------------------
extern "C" void kernel_launch(void* const* d_in, const int* in_sizes, int n_in,
                              void* d_out, int out_size)
{
    const float* nodes = (const float*)d_in[0];
    const float* W     = (const float*)d_in[1];
    const float* Wout  = (const float*)d_in[2];
    const float* bias  = (const float*)d_in[3];
    float* out = (float*)d_out;

    cudaFuncSetAttribute(k_mm_xw,  cudaFuncAttributeMaxDynamicSharedMemorySize, SMEM_SZ);
    cudaFuncSetAttribute(k_mm_out, cudaFuncAttributeMaxDynamicSharedMemorySize, SMEM_SZ);
    cudaFuncSetAttribute(k_flash,  cudaFuncAttributeMaxDynamicSharedMemorySize, FSMEM);

    k_split_nodes<<<(Bdim * Ndim * Fdim) / 256, 256>>>(nodes);
    k_cvt_WT<<<dim3(Fdim / 32, Fdim / 32, Hdim), 256>>>(W);
    k_cvt_WoT<<<dim3(Odim / 32, HF / 32, 1), 256>>>(Wout);

    k_mm_xw<<<dim3(Fdim / 128, Ndim / 128, BHdim), 256, SMEM_SZ>>>();
    k_flash<<<dim3(Ndim / 64, BHdim), 256, FSMEM>>>();
    k_mm_out<<<dim3(Odim / 128, (Bdim * Ndim) / 128, 1), 256, SMEM_SZ>>>(out, bias);
}

// round 15
// speedup vs baseline: 1.1402x; 1.1402x over previous
#include <cuda_runtime.h>
#include <cuda_fp16.h>
#include <cstdint>

typedef __half f16;

#define Bdim 4
#define Ndim 2048
#define Fdim 256
#define Odim 256
#define Hdim 8
#define BHdim 32
#define HF   2048

// ---------------- scratch (static device globals; no cudaMalloc) ----------
__device__ __align__(16) f16  g_Xhi [(size_t)Bdim*Ndim*Fdim];
__device__ __align__(16) f16  g_WThi[(size_t)Hdim*Fdim*Fdim];
__device__ __align__(16) f16  g_WoThi[(size_t)Odim*HF];
__device__ __align__(16) f16  g_mhi [(size_t)Bdim*Ndim*HF];

// ---------------- low-level helpers ----------------------------------------
__device__ __forceinline__ uint32_t smem_u32(const void* p) {
    uint32_t a;
    asm("{ .reg .u64 t; cvta.to.shared.u64 t, %1; cvt.u32.u64 %0, t; }"
        : "=r"(a) : "l"(p));
    return a;
}
#define SWZ(o) ((o) ^ (((o) >> 3) & 0x70))   // SW128: 16B-chunk ^= row%8

__device__ __forceinline__ void cp16(uint32_t dst, const void* src) {
    asm volatile("cp.async.cg.shared.global [%0], [%1], 16;" :: "r"(dst), "l"(src));
}
__device__ __forceinline__ void cp_commit() {
    asm volatile("cp.async.commit_group;");
}
template<int N> __device__ __forceinline__ void cp_wait() {
    asm volatile("cp.async.wait_group %0;" :: "n"(N) : "memory");
}
__device__ __forceinline__ void ldsm4(uint32_t& r0, uint32_t& r1, uint32_t& r2,
                                      uint32_t& r3, uint32_t addr) {
    asm volatile("ldmatrix.sync.aligned.m8n8.x4.shared.b16 {%0,%1,%2,%3}, [%4];"
                 : "=r"(r0), "=r"(r1), "=r"(r2), "=r"(r3) : "r"(addr));
}
__device__ __forceinline__ void ldsm4t(uint32_t& r0, uint32_t& r1, uint32_t& r2,
                                       uint32_t& r3, uint32_t addr) {
    asm volatile("ldmatrix.sync.aligned.m8n8.x4.trans.shared.b16 {%0,%1,%2,%3}, [%4];"
                 : "=r"(r0), "=r"(r1), "=r"(r2), "=r"(r3) : "r"(addr));
}
__device__ __forceinline__ void mma16816(float* c, const uint32_t* a, const uint32_t* b) {
    asm volatile(
        "mma.sync.aligned.m16n8k16.row.col.f32.f16.f16.f32 "
        "{%0,%1,%2,%3},{%4,%5,%6,%7},{%8,%9},{%0,%1,%2,%3};"
        : "+f"(c[0]), "+f"(c[1]), "+f"(c[2]), "+f"(c[3])
        : "r"(a[0]), "r"(a[1]), "r"(a[2]), "r"(a[3]), "r"(b[0]), "r"(b[1]));
}

#define TILE_B  16384                   // 128 rows x 64 f16 (128B rows)
#define STAGE_B (2 * TILE_B)            // A, B
#define SMEM_SZ (2 * STAGE_B)           // 65536 bytes, double buffered

// ---------------- plain fp16 HMMA GEMM core (out stage) ---------------------
// C(128x128) = A[m,k] * B[n,k]   (K-major, NT);  Cf = acc + bias
__device__ __forceinline__ void gemm_core_bias(
    const f16* __restrict__ A, int lda,
    const f16* __restrict__ B, int ldb,
    int K, float* __restrict__ Cf, int ldc, const float* __restrict__ bias)
{
    extern __shared__ char smem[];
    const uint32_t sb = smem_u32(smem);
    const int tid = threadIdx.x;
    const int wid = tid >> 5, lane = tid & 31;
    const int wm = wid >> 2, wn = wid & 3;        // warp grid 2 x 4
    const int bm = blockIdx.y * 128, bn = blockIdx.x * 128;

    auto load_chunk = [&](int stage, int k0) {
        const uint32_t sbase = sb + stage * STAGE_B;
#pragma unroll
        for (int i = 0; i < 8; i++) {
            int idx = i * 256 + tid;
            int arr = idx >> 10;                   // 0..1
            int r   = (idx >> 3) & 127;
            int c   = idx & 7;
            uint32_t dst = sbase + arr * TILE_B + SWZ((uint32_t)(r * 128 + c * 16));
            const f16* src = (arr == 0)
                ? A + (size_t)(bm + r) * lda + k0 + c * 8
                : B + (size_t)(bn + r) * ldb + k0 + c * 8;
            cp16(dst, src);
        }
        cp_commit();
    };

    float acc[4][4][4];
#pragma unroll
    for (int i = 0; i < 4; i++)
#pragma unroll
        for (int j = 0; j < 4; j++)
#pragma unroll
            for (int q = 0; q < 4; q++) acc[i][j][q] = 0.0f;

    const int NC = K >> 6;
    load_chunk(0, 0);

    const int a_row = wm * 64 + (lane & 15);
    const int a_c16 = (lane >> 4) * 16;
    const int b_row = wn * 32 + (lane & 7) + ((lane >> 4) << 3);
    const int b_c16 = ((lane >> 3) & 1) * 16;

    for (int c = 0; c < NC; c++) {
        const int stage = c & 1;
        if (c + 1 < NC) { load_chunk(stage ^ 1, (c + 1) * 64); cp_wait<1>(); }
        else            { cp_wait<0>(); }
        __syncthreads();

        const uint32_t sA = sb + stage * STAGE_B;
        const uint32_t sB = sA + TILE_B;

#pragma unroll
        for (int s4 = 0; s4 < 4; s4++) {
            const int kb = s4 * 32;
            uint32_t bhi[4][2];
#pragma unroll
            for (int jj = 0; jj < 2; jj++) {
                uint32_t off = SWZ((uint32_t)((b_row + jj * 16) * 128 + kb + b_c16));
                ldsm4(bhi[jj*2][0], bhi[jj*2][1], bhi[jj*2+1][0], bhi[jj*2+1][1], sB + off);
            }
#pragma unroll
            for (int i = 0; i < 4; i++) {
                uint32_t off = SWZ((uint32_t)((a_row + i * 16) * 128 + kb + a_c16));
                uint32_t ahi[4];
                ldsm4(ahi[0], ahi[1], ahi[2], ahi[3], sA + off);
#pragma unroll
                for (int j = 0; j < 4; j++)
                    mma16816(acc[i][j], ahi, bhi[j]);
            }
        }
        __syncthreads();
    }

    const int er = lane >> 2;
    const int ec = (lane & 3) * 2;
#pragma unroll
    for (int i = 0; i < 4; i++) {
#pragma unroll
        for (int j = 0; j < 4; j++) {
            const int n0 = bn + wn * 32 + j * 8 + ec;
#pragma unroll
            for (int half = 0; half < 2; half++) {
                const int m = bm + wm * 64 + i * 16 + er + half * 8;
                float v0 = acc[i][j][half * 2 + 0];
                float v1 = acc[i][j][half * 2 + 1];
                size_t go = (size_t)m * ldc + n0;
                float2 o; o.x = v0 + bias[n0]; o.y = v1 + bias[n0 + 1];
                *(float2*)(Cf + go) = o;
            }
        }
    }
}

__global__ __launch_bounds__(256, 1) void k_mm_out(float* __restrict__ out,
                                                   const float* __restrict__ bias) {
    gemm_core_bias(g_mhi, HF, g_WoThi, HF, HF, out, Odim, bias);
}

// ============================================================================
// Fused: Q-projection (X·W_h) prologue + flash attention (unnormalized
// softmax), occ 1, double-buffered K.
// Prologue: X strip (32K) -> FQ region, W_h (128K) -> K region; Q computed
// into oacc registers, written f16-swizzled over FQ; K(0) load overlaps.
// Main loop (R13): [cp_wait+sync] prefetch K(t+1) | S-MMA | exp+P | [sync] PV.
// SMEM: Q 32K | K 2 x 64K | P 16K | red 1K = 177K
// ============================================================================
#define FQoff 0
#define FKoff 32768
#define FPoff 163840
#define RSUMoff 180224
#define FSMEM 181248

__global__ __launch_bounds__(256, 1) void k_flash() {
    extern __shared__ char smem[];
    const uint32_t sb = smem_u32(smem);
    const int tid = threadIdx.x, lane = tid & 31, wid = tid >> 5;
    const int wm = wid >> 2, wn = wid & 3;
    const int z = blockIdx.y, b = z >> 3, h = z & 7;
    const int qb = blockIdx.x;

    const f16* Xb = g_Xhi  + (size_t)b * Ndim * Fdim;
    const f16* Wh = g_WThi + (size_t)h * Fdim * Fdim;

    // ---- prologue loads: X strip -> FQ (4 chunks 64x64), W_h -> K region ----
#pragma unroll
    for (int i = 0; i < 8; i++) {
        int idx = i * 256 + tid;
        int kc = idx >> 9;
        int r = (idx >> 3) & 63, cc = idx & 7;
        const f16* src = Xb + (size_t)(qb * 64 + r) * Fdim + kc * 64 + cc * 8;
        cp16(sb + FQoff + kc * 8192 + SWZ((uint32_t)(r * 128 + cc * 16)), src);
    }
#pragma unroll
    for (int i = 0; i < 32; i++) {            // W: 8 tiles (fi-chunk c, fo-half fh)
        int idx = i * 256 + tid;
        int tile = idx >> 10;                  // 0..7 = c*2+fh
        int c = tile >> 1, fh = tile & 1;
        int r = (idx >> 3) & 127, cc = idx & 7;
        const f16* src = Wh + (size_t)(fh * 128 + r) * Fdim + c * 64 + cc * 8;
        cp16(sb + FKoff + tile * 16384 + SWZ((uint32_t)(r * 128 + cc * 16)), src);
    }
    cp_commit();

    const int a_row  = wm * 32 + (lane & 15);
    const int a_c16  = (lane >> 4) * 16;
    const int bk_row = wn * 32 + (lane & 7) + ((lane >> 4) << 3);
    const int b_c16  = ((lane >> 3) & 1) * 16;
    const int tv_row = lane & 15;
    const int tv_c16 = (lane >> 4) * 16;

    // oacc doubles as qacc during the prologue
    float oacc[2][8][4];
#pragma unroll
    for (int i = 0; i < 2; i++)
#pragma unroll
        for (int j = 0; j < 8; j++)
#pragma unroll
            for (int q = 0; q < 4; q++) oacc[i][j][q] = 0.0f;

    cp_wait<0>(); __syncthreads();             // X + W resident

    // ---- Q = X · W_h^T  (64x256x256 NT; warp tile 32 x 64) ----
    {
        const int wb_row = (wn & 1) * 64 + (lane & 7) + ((lane >> 4) << 3);
        const uint32_t wbase = sb + FKoff + (wn >> 1) * 16384;
#pragma unroll
        for (int c = 0; c < 4; c++) {
            uint32_t xh = sb + FQoff + c * 8192;
            uint32_t wh_ = wbase + c * 32768;
#pragma unroll
            for (int s4 = 0; s4 < 4; s4++) {
                int kb2 = s4 * 32;
                uint32_t bh[8][2];
#pragma unroll
                for (int jj = 0; jj < 4; jj++) {
                    uint32_t off = SWZ((uint32_t)((wb_row + jj * 16) * 128 + kb2 + b_c16));
                    ldsm4(bh[jj*2][0], bh[jj*2][1], bh[jj*2+1][0], bh[jj*2+1][1], wh_ + off);
                }
#pragma unroll
                for (int i = 0; i < 2; i++) {
                    uint32_t off = SWZ((uint32_t)((a_row + i * 16) * 128 + kb2 + a_c16));
                    uint32_t ah[4];
                    ldsm4(ah[0], ah[1], ah[2], ah[3], xh + off);
#pragma unroll
                    for (int j = 0; j < 8; j++)
                        mma16816(oacc[i][j], ah, bh[j]);
                }
            }
        }
    }
    __syncthreads();                           // X (FQ) & W (K) reads done

    const f16* Khi = Xb;                       // K = X
    auto load_K_tile = [&](int buf, int kv0) {
        const uint32_t kb = sb + FKoff + buf * 65536;
#pragma unroll
        for (int i = 0; i < 16; i++) {
            int idx = i * 256 + tid;
            int c = idx >> 10;
            int r = (idx >> 3) & 127, cc = idx & 7;
            const f16* src = Khi + (size_t)(kv0 + r) * Fdim + c * 64 + cc * 8;
            cp16(kb + c * 16384 + SWZ((uint32_t)(r * 128 + cc * 16)), src);
        }
        cp_commit();
    };
    load_K_tile(0, 0);                         // overlaps Q writeback

    // ---- write Q (f16) over FQ: warp wn owns chunk wn ----
#pragma unroll
    for (int i = 0; i < 2; i++)
#pragma unroll
        for (int j = 0; j < 8; j++)
#pragma unroll
            for (int hf = 0; hf < 2; hf++) {
                int r = wm * 32 + i * 16 + (lane >> 2) + hf * 8;
                int cc = j * 8 + (lane & 3) * 2;
                uint32_t off = SWZ((uint32_t)(r * 128 + cc * 2));
                *(__half2*)(smem + FQoff + wn * 8192 + off) =
                    __halves2half2(__float2half_rn(oacc[i][j][hf * 2]),
                                   __float2half_rn(oacc[i][j][hf * 2 + 1]));
            }
    __syncthreads();                           // Q visible

    // zero O for the attention loop
#pragma unroll
    for (int i = 0; i < 2; i++)
#pragma unroll
        for (int j = 0; j < 8; j++)
#pragma unroll
            for (int q = 0; q < 4; q++) oacc[i][j][q] = 0.0f;
    float sacc[2][4][4];
    float lsum[2][2] = {{0.f, 0.f}, {0.f, 0.f}};

    float* redsum = (float*)(smem + RSUMoff);

    for (int t = 0; t < 16; t++) {
        const int buf = t & 1;
        const uint32_t kbase = sb + FKoff + buf * 65536;

        cp_wait<0>();
        __syncthreads();                      // K(t) ready; PV(t-1) reads done

        if (t + 1 < 16) load_K_tile(buf ^ 1, (t + 1) * 128);

        // ---- S = Q·K over all 4 f-chunks ----
#pragma unroll
        for (int i = 0; i < 2; i++)
#pragma unroll
            for (int j = 0; j < 4; j++)
#pragma unroll
                for (int q = 0; q < 4; q++) sacc[i][j][q] = 0.0f;
#pragma unroll
        for (int c = 0; c < 4; c++) {
            uint32_t qh = sb + FQoff + c * 8192;
            uint32_t kh = kbase + c * 16384;
#pragma unroll
            for (int s4 = 0; s4 < 4; s4++) {
                int kb2 = s4 * 32;
                uint32_t bh[4][2];
#pragma unroll
                for (int jj = 0; jj < 2; jj++) {
                    uint32_t off = SWZ((uint32_t)((bk_row + jj * 16) * 128 + kb2 + b_c16));
                    ldsm4(bh[jj*2][0], bh[jj*2][1], bh[jj*2+1][0], bh[jj*2+1][1], kh + off);
                }
#pragma unroll
                for (int i = 0; i < 2; i++) {
                    uint32_t off = SWZ((uint32_t)((a_row + i * 16) * 128 + kb2 + a_c16));
                    uint32_t ah[4];
                    ldsm4(ah[0], ah[1], ah[2], ah[3], qh + off);
#pragma unroll
                    for (int j = 0; j < 4; j++)
                        mma16816(sacc[i][j], ah, bh[j]);
                }
            }
        }

        // ---- unnormalized softmax: P = exp(S/16) ----
#pragma unroll
        for (int i = 0; i < 2; i++)
#pragma unroll
            for (int j = 0; j < 4; j++) {
                float p00 = __expf(sacc[i][j][0] * 0.0625f);
                float p01 = __expf(sacc[i][j][1] * 0.0625f);
                float p10 = __expf(sacc[i][j][2] * 0.0625f);
                float p11 = __expf(sacc[i][j][3] * 0.0625f);
                lsum[i][0] += p00 + p01;
                lsum[i][1] += p10 + p11;
                int col = wn * 32 + j * 8 + (lane & 3) * 2;
                int chunk = col >> 6, cc = col & 63;
#pragma unroll
                for (int hf = 0; hf < 2; hf++) {
                    int r = wm * 32 + i * 16 + (lane >> 2) + hf * 8;
                    uint32_t off = SWZ((uint32_t)(r * 128 + cc * 2));
                    *(__half2*)(smem + FPoff + chunk * 8192 + off) =
                        (hf == 0) ? __halves2half2(__float2half_rn(p00), __float2half_rn(p01))
                                  : __halves2half2(__float2half_rn(p10), __float2half_rn(p11));
                }
            }
        __syncthreads();                      // P visible

        // ---- PV: O += P · K^T (V = K chunk wn via ldmatrix.trans) ----
        {
            uint32_t vh = kbase + wn * 16384;
#pragma unroll
            for (int kc = 0; kc < 2; kc++) {
                uint32_t ph = sb + FPoff + kc * 8192;
#pragma unroll
                for (int s4 = 0; s4 < 4; s4++) {
                    int kr = kc * 64 + s4 * 16;
                    uint32_t bh[8][2];
#pragma unroll
                    for (int jh = 0; jh < 4; jh++) {
                        uint32_t off = SWZ((uint32_t)((kr + tv_row) * 128 + jh * 32 + tv_c16));
                        ldsm4t(bh[jh*2][0], bh[jh*2][1], bh[jh*2+1][0], bh[jh*2+1][1], vh + off);
                    }
#pragma unroll
                    for (int i = 0; i < 2; i++) {
                        uint32_t off = SWZ((uint32_t)((a_row + i * 16) * 128 + s4 * 32 + a_c16));
                        uint32_t p4h[4];
                        ldsm4(p4h[0], p4h[1], p4h[2], p4h[3], ph + off);
#pragma unroll
                        for (int j = 0; j < 8; j++)
                            mma16816(oacc[i][j], p4h, bh[j]);
                    }
                }
            }
        }
    }

    // ---- epilogue: reduce lsum, then O/l -> g_mhi ----
#pragma unroll
    for (int i = 0; i < 2; i++)
#pragma unroll
        for (int hf = 0; hf < 2; hf++) {
            float ts = lsum[i][hf];
            ts += __shfl_xor_sync(0xffffffffu, ts, 1);
            ts += __shfl_xor_sync(0xffffffffu, ts, 2);
            if ((lane & 3) == 0) {
                int r = wm * 32 + i * 16 + (lane >> 2) + hf * 8;
                redsum[wn * 64 + r] = ts;
            }
        }
    __syncthreads();

#pragma unroll
    for (int i = 0; i < 2; i++)
#pragma unroll
        for (int hf = 0; hf < 2; hf++) {
            int r = wm * 32 + i * 16 + (lane >> 2) + hf * 8;
            int n = qb * 64 + r;
            float l = redsum[r] + redsum[64 + r] + redsum[128 + r] + redsum[192 + r];
            float invl = 1.0f / l;
#pragma unroll
            for (int j = 0; j < 8; j++) {
                int col = h * 256 + wn * 64 + j * 8 + (lane & 3) * 2;
                float v0 = oacc[i][j][hf * 2] * invl;
                float v1 = oacc[i][j][hf * 2 + 1] * invl;
                size_t go = ((size_t)b * Ndim + n) * HF + col;
                *(__half2*)(g_mhi + go) =
                    __halves2half2(__float2half_rn(v0), __float2half_rn(v1));
            }
        }
}

// ---------------- convert / transpose-convert -------------------------------
__global__ __launch_bounds__(256) void k_split_nodes(const float* __restrict__ x) {
    int i = blockIdx.x * 256 + threadIdx.x;
    g_Xhi[i] = __float2half_rn(x[i]);
}

__device__ __forceinline__ void tcvt_core(const float* __restrict__ src,
                                          f16* __restrict__ hi, int R, int C) {
    __shared__ float t[32][33];
    size_t mo = (size_t)blockIdx.z * R * C;
    src += mo; hi += mo;
    int c0 = blockIdx.x * 32, r0 = blockIdx.y * 32;
    int tx = threadIdx.x & 31, ty = threadIdx.x >> 5;
#pragma unroll
    for (int k = 0; k < 4; k++)
        t[ty + k * 8][tx] = src[(size_t)(r0 + ty + k * 8) * C + c0 + tx];
    __syncthreads();
#pragma unroll
    for (int k = 0; k < 4; k++) {
        int rr = ty + k * 8;
        hi[(size_t)(c0 + rr) * R + r0 + tx] = __float2half_rn(t[tx][rr]);
    }
}
__global__ __launch_bounds__(256) void k_cvt_WT(const float* __restrict__ W) {
    tcvt_core(W, g_WThi, Fdim, Fdim);
}
__global__ __launch_bounds__(256) void k_cvt_WoT(const float* __restrict__ Wo) {
    tcvt_core(Wo, g_WoThi, HF, Odim);
}

// ---------------- launch ------------------------------------------------------
extern "C" void kernel_launch(void* const* d_in, const int* in_sizes, int n_in,
                              void* d_out, int out_size)
{
    const float* nodes = (const float*)d_in[0];
    const float* W     = (const float*)d_in[1];
    const float* Wout  = (const float*)d_in[2];
    const float* bias  = (const float*)d_in[3];
    float* out = (float*)d_out;

    cudaFuncSetAttribute(k_mm_out, cudaFuncAttributeMaxDynamicSharedMemorySize, SMEM_SZ);
    cudaFuncSetAttribute(k_flash,  cudaFuncAttributeMaxDynamicSharedMemorySize, FSMEM);

    k_split_nodes<<<(Bdim * Ndim * Fdim) / 256, 256>>>(nodes);
    k_cvt_WT<<<dim3(Fdim / 32, Fdim / 32, Hdim), 256>>>(W);
    k_cvt_WoT<<<dim3(Odim / 32, HF / 32, 1), 256>>>(Wout);

    k_flash<<<dim3(Ndim / 64, BHdim), 256, FSMEM>>>();
    k_mm_out<<<dim3(Odim / 128, (Bdim * Ndim) / 128, 1), 256, SMEM_SZ>>>(out, bias);
}